// round 17
// baseline (speedup 1.0000x reference)
#include <cuda_runtime.h>
#include <cuda_fp16.h>
#include <cstdint>

#define DF 128
#define NMAX 100000
#define EMAX 1600000
#define GMAX 1024
#define XS_STRIDE 144

// persistent scratch (no allocations allowed)
__device__ __half g_h16a[(size_t)NMAX * DF];
__device__ __half g_h16b[(size_t)NMAX * DF];
__device__ float  g_pool[(size_t)GMAX * DF];
__device__ int    g_deg[NMAX];
__device__ int    g_rowptr[NMAX + 1];
__device__ int    g_cursor[NMAX];
__device__ int    g_csrc[EMAX];
__device__ int    g_bsum[1024];

#define BAR_SYNC(id, cnt)   asm volatile("bar.sync %0, %1;"   :: "r"(id), "r"(cnt) : "memory")
#define BAR_ARRIVE(id, cnt) asm volatile("bar.arrive %0, %1;" :: "r"(id), "r"(cnt) : "memory")

// ---------------------------------------------------------------------------
// CSR build: degree histogram -> exclusive scan -> scatter
__global__ void deg_kernel(const int* __restrict__ dst, int* __restrict__ deg, int E) {
    int i = blockIdx.x * blockDim.x + threadIdx.x;
    if (i < E) atomicAdd(&deg[__ldg(dst + i)], 1);
}

__global__ void scan1_kernel(const int* __restrict__ deg, int* __restrict__ rowptr,
                             int* __restrict__ bsum, int N) {
    __shared__ int sh[1024];
    int tid = threadIdx.x;
    int i = blockIdx.x * 1024 + tid;
    int v = (i < N) ? deg[i] : 0;
    sh[tid] = v;
    __syncthreads();
    #pragma unroll
    for (int off = 1; off < 1024; off <<= 1) {
        int t = (tid >= off) ? sh[tid - off] : 0;
        __syncthreads();
        sh[tid] += t;
        __syncthreads();
    }
    if (i < N) rowptr[i] = sh[tid] - v;
    if (tid == 1023) bsum[blockIdx.x] = sh[1023];
}

__global__ void scan2_kernel(int* __restrict__ bsum, int nb) {
    if (threadIdx.x == 0 && blockIdx.x == 0) {
        int acc = 0;
        for (int i = 0; i < nb; ++i) {
            int v = bsum[i];
            bsum[i] = acc;
            acc += v;
        }
    }
}

__global__ void scan3_kernel(int* __restrict__ rowptr, const int* __restrict__ bsum,
                             int* __restrict__ cursor, int N, int E) {
    int i = blockIdx.x * 1024 + threadIdx.x;
    if (i < N) {
        int v = rowptr[i] + bsum[blockIdx.x];
        rowptr[i] = v;
        cursor[i] = v;
    }
    if (i == 0) rowptr[N] = E;
}

__global__ void scatter_kernel(const int* __restrict__ src, const int* __restrict__ dst,
                               int* __restrict__ cursor, int* __restrict__ csrc, int E) {
    int i = blockIdx.x * blockDim.x + threadIdx.x;
    if (i < E) {
        int pos = atomicAdd(&cursor[__ldg(dst + i)], 1);
        csrc[pos] = __ldg(src + i);
    }
}

// ---------------------------------------------------------------------------
__global__ void cvt16_kernel(const float* __restrict__ src, __half* __restrict__ dst, int n4) {
    int i = blockIdx.x * blockDim.x + threadIdx.x;
    if (i < n4) {
        float4 v = *(const float4*)(src + i * 4);
        __half2 p2[2];
        p2[0] = __floats2half2_rn(v.x, v.y);
        p2[1] = __floats2half2_rn(v.z, v.w);
        *(float2*)(dst + i * 4) = *(float2*)p2;
    }
}

// ---------------------------------------------------------------------------
__device__ __forceinline__ void acc8(float* acc, uint4 p) {
    float2 f0 = __half22float2(*(__half2*)&p.x);
    float2 f1 = __half22float2(*(__half2*)&p.y);
    float2 f2 = __half22float2(*(__half2*)&p.z);
    float2 f3 = __half22float2(*(__half2*)&p.w);
    acc[0] += f0.x; acc[1] += f0.y;
    acc[2] += f1.x; acc[3] += f1.y;
    acc[4] += f2.x; acc[5] += f2.y;
    acc[6] += f3.x; acc[7] += f3.y;
}

// ---------------------------------------------------------------------------
// Warp-specialized fused GIN layer: 1024 threads, triple-buffered Xs + Cs.
// Warps 0-23 (producers, 48 half-warp chains): gather + residual into Xs[buf].
// Warps 24-31 (consumers): HMMA MLP (two 64-col halves) into Cs, LN/ReLU x2.
// full[buf]=1+buf, empty[buf]=4+buf (count 1024); consumer barrier 7 (count 256).
#define NPROD 24
#define NCONS 8

__global__ void __launch_bounds__(1024, 1)
layer_fused(const __half* __restrict__ hin16,
            const int* __restrict__ rowptr, const int* __restrict__ csrc,
            const float* __restrict__ epsArr, int layer,
            const float* __restrict__ W1, const float* __restrict__ b1,
            const float* __restrict__ g1, const float* __restrict__ be1,
            const float* __restrict__ W2, const float* __restrict__ b2,
            const float* __restrict__ ng, const float* __restrict__ nb,
            __half* __restrict__ out16,
            int nrows, int ntiles) {
    extern __shared__ __align__(16) char smraw[];
    __half* Ws1 = (__half*)smraw;                        // 16384 halfs
    __half* Ws2 = Ws1 + 128 * 128;                       // 16384 halfs
    __half* XsB = Ws2 + 128 * 128;                       // 3 x 128*144 halfs
    __half* Cs  = XsB + 3 * 128 * XS_STRIDE;             // 128*144 halfs
    float*  prm = (float*)(Cs + 128 * XS_STRIDE);        // 6*128 floats
    float* bs1 = prm, *gs1 = prm + 128, *es1 = prm + 256;
    float* bs2 = prm + 384, *gs2 = prm + 512, *es2 = prm + 640;

    int tid  = threadIdx.x;
    int lane = tid & 31, warp = tid >> 5;

    // Stage W1/W2 as half, interleaved: Ws[(s*128+n)*16 + pos(k&15)]
    for (int idx = tid; idx < 4096; idx += 1024) {
        int k  = idx >> 5;
        int n4 = idx & 31;
        int s  = k >> 4, kq = k & 15;
        int pos = (kq & 1) | (((kq >> 3) & 1) << 1) | (((kq >> 1) & 3) << 2);
        size_t go = (size_t)k * DF + n4 * 4;
        float4 wa = *(const float4*)(W1 + go);
        float4 wb = *(const float4*)(W2 + go);
        int base = ((s * 128) + n4 * 4) * 16 + pos;
        Ws1[base]      = __float2half(wa.x);
        Ws1[base + 16] = __float2half(wa.y);
        Ws1[base + 32] = __float2half(wa.z);
        Ws1[base + 48] = __float2half(wa.w);
        Ws2[base]      = __float2half(wb.x);
        Ws2[base + 16] = __float2half(wb.y);
        Ws2[base + 32] = __float2half(wb.z);
        Ws2[base + 48] = __float2half(wb.w);
    }
    if (tid < DF) {
        bs1[tid] = b1[tid]; gs1[tid] = g1[tid]; es1[tid] = be1[tid];
        bs2[tid] = b2[tid]; gs2[tid] = ng[tid]; es2[tid] = nb[tid];
    }
    __syncthreads();

    float escale = 1.0f + epsArr[layer];

    if (warp < NPROD) {
        // ======================= PRODUCER =======================
        int hw   = lane >> 4;
        int hl   = lane & 15;
        int hwid = warp * 2 + hw;       // 0..47
        int lt = 0;
        for (int tile = blockIdx.x; tile < ntiles; tile += gridDim.x, ++lt) {
            int buf = lt % 3;
            if (lt >= 3) BAR_SYNC(4 + buf, 1024);      // wait empty[buf]
            __half* Xs = XsB + buf * (128 * XS_STRIDE);
            int rowBlk = tile * 128;
            for (int r = hwid; r < 128; r += 48) {
                int row = rowBlk + r;
                float acc[8] = {0.f, 0.f, 0.f, 0.f, 0.f, 0.f, 0.f, 0.f};
                if (row < nrows) {
                    int beg = __ldg(rowptr + row), end = __ldg(rowptr + row + 1);
                    int i = beg;
                    for (; i + 8 <= end; i += 8) {
                        int u0 = __ldg(csrc + i),     u1 = __ldg(csrc + i + 1);
                        int u2 = __ldg(csrc + i + 2), u3 = __ldg(csrc + i + 3);
                        int u4 = __ldg(csrc + i + 4), u5 = __ldg(csrc + i + 5);
                        int u6 = __ldg(csrc + i + 6), u7 = __ldg(csrc + i + 7);
                        uint4 p0 = *(const uint4*)(hin16 + (size_t)u0 * DF + hl * 8);
                        uint4 p1 = *(const uint4*)(hin16 + (size_t)u1 * DF + hl * 8);
                        uint4 p2 = *(const uint4*)(hin16 + (size_t)u2 * DF + hl * 8);
                        uint4 p3 = *(const uint4*)(hin16 + (size_t)u3 * DF + hl * 8);
                        uint4 p4 = *(const uint4*)(hin16 + (size_t)u4 * DF + hl * 8);
                        uint4 p5 = *(const uint4*)(hin16 + (size_t)u5 * DF + hl * 8);
                        uint4 p6 = *(const uint4*)(hin16 + (size_t)u6 * DF + hl * 8);
                        uint4 p7 = *(const uint4*)(hin16 + (size_t)u7 * DF + hl * 8);
                        acc8(acc, p0); acc8(acc, p1); acc8(acc, p2); acc8(acc, p3);
                        acc8(acc, p4); acc8(acc, p5); acc8(acc, p6); acc8(acc, p7);
                    }
                    for (; i + 4 <= end; i += 4) {
                        int u0 = __ldg(csrc + i),     u1 = __ldg(csrc + i + 1);
                        int u2 = __ldg(csrc + i + 2), u3 = __ldg(csrc + i + 3);
                        uint4 p0 = *(const uint4*)(hin16 + (size_t)u0 * DF + hl * 8);
                        uint4 p1 = *(const uint4*)(hin16 + (size_t)u1 * DF + hl * 8);
                        uint4 p2 = *(const uint4*)(hin16 + (size_t)u2 * DF + hl * 8);
                        uint4 p3 = *(const uint4*)(hin16 + (size_t)u3 * DF + hl * 8);
                        acc8(acc, p0); acc8(acc, p1); acc8(acc, p2); acc8(acc, p3);
                    }
                    for (; i < end; ++i) {
                        int u = __ldg(csrc + i);
                        uint4 p = *(const uint4*)(hin16 + (size_t)u * DF + hl * 8);
                        acc8(acc, p);
                    }
                    uint4 hp = *(const uint4*)(hin16 + (size_t)row * DF + hl * 8);
                    float2 h0 = __half22float2(*(__half2*)&hp.x);
                    float2 h1 = __half22float2(*(__half2*)&hp.y);
                    float2 h2 = __half22float2(*(__half2*)&hp.z);
                    float2 h3 = __half22float2(*(__half2*)&hp.w);
                    acc[0] = fmaf(escale, h0.x, acc[0]);
                    acc[1] = fmaf(escale, h0.y, acc[1]);
                    acc[2] = fmaf(escale, h1.x, acc[2]);
                    acc[3] = fmaf(escale, h1.y, acc[3]);
                    acc[4] = fmaf(escale, h2.x, acc[4]);
                    acc[5] = fmaf(escale, h2.y, acc[5]);
                    acc[6] = fmaf(escale, h3.x, acc[6]);
                    acc[7] = fmaf(escale, h3.y, acc[7]);
                }
                #pragma unroll
                for (int cc = 0; cc < 2; ++cc) {
                    int c4 = 2 * hl + cc;
                    int a = (c4 & 1) * 8 + (c4 & 2);
                    __half* p = Xs + r * XS_STRIDE + (c4 >> 2) * 16 + a;
                    float* A = acc + cc * 4;
                    *(__half2*)p       = __floats2half2_rn(A[0], A[1]);
                    *(__half2*)(p + 4) = __floats2half2_rn(A[2], A[3]);
                }
            }
            BAR_ARRIVE(1 + buf, 1024);                 // signal full[buf]
        }
    } else {
        // ======================= CONSUMER =======================
        int cw = warp - NPROD;          // 0..7
        int wr = cw * 16;
        int fr = lane >> 2;
        int qd = lane & 3;
        int lt = 0;
        for (int tile = blockIdx.x; tile < ntiles; tile += gridDim.x, ++lt) {
            int buf = lt % 3;
            BAR_SYNC(1 + buf, 1024);                   // wait full[buf]
            __half* Xs = XsB + buf * (128 * XS_STRIDE);
            int rowBlk = tile * 128;

            // ---- pass 1: X @ W1 -> Cs (two 64-col halves) ----
            #pragma unroll
            for (int ch = 0; ch < 2; ++ch) {
                int wc = ch * 64;
                float acc[8][4];
                #pragma unroll
                for (int j = 0; j < 8; ++j) {
                    acc[j][0] = 0.f; acc[j][1] = 0.f; acc[j][2] = 0.f; acc[j][3] = 0.f;
                }
                #pragma unroll
                for (int s = 0; s < 8; ++s) {
                    uint2 av0 = *(const uint2*)(Xs + (wr + fr)     * XS_STRIDE + s * 16 + qd * 4);
                    uint2 av1 = *(const uint2*)(Xs + (wr + fr + 8) * XS_STRIDE + s * 16 + qd * 4);
                    #pragma unroll
                    for (int j = 0; j < 8; ++j) {
                        uint2 bv = *(const uint2*)(Ws1 + ((s * 128) + wc + j * 8 + fr) * 16 + qd * 4);
                        asm volatile(
                            "mma.sync.aligned.m16n8k16.row.col.f32.f16.f16.f32 "
                            "{%0,%1,%2,%3}, {%4,%5,%6,%7}, {%8,%9}, {%0,%1,%2,%3};"
                            : "+f"(acc[j][0]), "+f"(acc[j][1]), "+f"(acc[j][2]), "+f"(acc[j][3])
                            : "r"(av0.x), "r"(av1.x), "r"(av0.y), "r"(av1.y),
                              "r"(bv.x), "r"(bv.y));
                    }
                }
                #pragma unroll
                for (int j = 0; j < 8; ++j) {
                    int n = wc + j * 8 + qd * 2;
                    *(__half2*)(Cs + (wr + fr)     * XS_STRIDE + n) = __floats2half2_rn(acc[j][0], acc[j][1]);
                    *(__half2*)(Cs + (wr + fr + 8) * XS_STRIDE + n) = __floats2half2_rn(acc[j][2], acc[j][3]);
                }
            }
            BAR_SYNC(7, 256);

            // ---- LN1 + ReLU: Cs (natural) -> Xs (interleaved) ----
            {
                float4 b4 = ((const float4*)bs1)[lane];
                float4 g4 = ((const float4*)gs1)[lane];
                float4 e4 = ((const float4*)es1)[lane];
                #pragma unroll
                for (int rr = 0; rr < 16; ++rr) {
                    int lrow = cw * 16 + rr;
                    const __half2* qq2 = (const __half2*)(Cs + lrow * XS_STRIDE + lane * 4);
                    float2 f0 = __half22float2(qq2[0]);
                    float2 f1 = __half22float2(qq2[1]);
                    float a0 = f0.x + b4.x, a1 = f0.y + b4.y, a2 = f1.x + b4.z, a3 = f1.y + b4.w;
                    float s = a0 + a1 + a2 + a3;
                    float q = a0 * a0 + a1 * a1 + a2 * a2 + a3 * a3;
                    #pragma unroll
                    for (int off = 16; off > 0; off >>= 1) {
                        s += __shfl_xor_sync(0xFFFFFFFFu, s, off);
                        q += __shfl_xor_sync(0xFFFFFFFFu, q, off);
                    }
                    float mu   = s * (1.0f / 128.0f);
                    float var  = q * (1.0f / 128.0f) - mu * mu;
                    float rstd = rsqrtf(var + 1e-5f);
                    float o0 = fmaxf(0.f, (a0 - mu) * rstd * g4.x + e4.x);
                    float o1 = fmaxf(0.f, (a1 - mu) * rstd * g4.y + e4.y);
                    float o2 = fmaxf(0.f, (a2 - mu) * rstd * g4.z + e4.z);
                    float o3 = fmaxf(0.f, (a3 - mu) * rstd * g4.w + e4.w);
                    int a = (lane & 1) * 8 + (lane & 2);
                    __half* p = Xs + lrow * XS_STRIDE + (lane >> 2) * 16 + a;
                    *(__half2*)p       = __floats2half2_rn(o0, o1);
                    *(__half2*)(p + 4) = __floats2half2_rn(o2, o3);
                }
            }
            BAR_SYNC(7, 256);

            // ---- pass 2: Y @ W2 -> Cs ----
            #pragma unroll
            for (int ch = 0; ch < 2; ++ch) {
                int wc = ch * 64;
                float acc[8][4];
                #pragma unroll
                for (int j = 0; j < 8; ++j) {
                    acc[j][0] = 0.f; acc[j][1] = 0.f; acc[j][2] = 0.f; acc[j][3] = 0.f;
                }
                #pragma unroll
                for (int s = 0; s < 8; ++s) {
                    uint2 av0 = *(const uint2*)(Xs + (wr + fr)     * XS_STRIDE + s * 16 + qd * 4);
                    uint2 av1 = *(const uint2*)(Xs + (wr + fr + 8) * XS_STRIDE + s * 16 + qd * 4);
                    #pragma unroll
                    for (int j = 0; j < 8; ++j) {
                        uint2 bv = *(const uint2*)(Ws2 + ((s * 128) + wc + j * 8 + fr) * 16 + qd * 4);
                        asm volatile(
                            "mma.sync.aligned.m16n8k16.row.col.f32.f16.f16.f32 "
                            "{%0,%1,%2,%3}, {%4,%5,%6,%7}, {%8,%9}, {%0,%1,%2,%3};"
                            : "+f"(acc[j][0]), "+f"(acc[j][1]), "+f"(acc[j][2]), "+f"(acc[j][3])
                            : "r"(av0.x), "r"(av1.x), "r"(av0.y), "r"(av1.y),
                              "r"(bv.x), "r"(bv.y));
                    }
                }
                #pragma unroll
                for (int j = 0; j < 8; ++j) {
                    int n = wc + j * 8 + qd * 2;
                    *(__half2*)(Cs + (wr + fr)     * XS_STRIDE + n) = __floats2half2_rn(acc[j][0], acc[j][1]);
                    *(__half2*)(Cs + (wr + fr + 8) * XS_STRIDE + n) = __floats2half2_rn(acc[j][2], acc[j][3]);
                }
            }
            BAR_SYNC(7, 256);
            BAR_ARRIVE(4 + buf, 1024);                 // Xs no longer needed -> empty[buf]

            // ---- LN2 + ReLU: Cs -> fp16 gmem ----
            {
                float4 b4 = ((const float4*)bs2)[lane];
                float4 g4 = ((const float4*)gs2)[lane];
                float4 e4 = ((const float4*)es2)[lane];
                #pragma unroll
                for (int rr = 0; rr < 16; ++rr) {
                    int lrow = cw * 16 + rr;
                    int grow = rowBlk + lrow;
                    const __half2* qq2 = (const __half2*)(Cs + lrow * XS_STRIDE + lane * 4);
                    float2 f0 = __half22float2(qq2[0]);
                    float2 f1 = __half22float2(qq2[1]);
                    float a0 = f0.x + b4.x, a1 = f0.y + b4.y, a2 = f1.x + b4.z, a3 = f1.y + b4.w;
                    float s = a0 + a1 + a2 + a3;
                    float q = a0 * a0 + a1 * a1 + a2 * a2 + a3 * a3;
                    #pragma unroll
                    for (int off = 16; off > 0; off >>= 1) {
                        s += __shfl_xor_sync(0xFFFFFFFFu, s, off);
                        q += __shfl_xor_sync(0xFFFFFFFFu, q, off);
                    }
                    float mu   = s * (1.0f / 128.0f);
                    float var  = q * (1.0f / 128.0f) - mu * mu;
                    float rstd = rsqrtf(var + 1e-5f);
                    float o0 = fmaxf(0.f, (a0 - mu) * rstd * g4.x + e4.x);
                    float o1 = fmaxf(0.f, (a1 - mu) * rstd * g4.y + e4.y);
                    float o2 = fmaxf(0.f, (a2 - mu) * rstd * g4.z + e4.z);
                    float o3 = fmaxf(0.f, (a3 - mu) * rstd * g4.w + e4.w);
                    if (grow < nrows) {
                        __half2 p2[2];
                        p2[0] = __floats2half2_rn(o0, o1);
                        p2[1] = __floats2half2_rn(o2, o3);
                        *(float2*)(out16 + (size_t)grow * DF + lane * 4) = *(float2*)p2;
                    }
                }
            }
            // Cs is consumer-private; next tile's pass1 waits on full[buf'] anyway,
            // and Cs reuse is ordered by the consumer-internal barrier at pass1 store.
            BAR_SYNC(7, 256);
        }
    }
}

// ---------------------------------------------------------------------------
__global__ void pool_kernel(const __half* __restrict__ h16, const int* __restrict__ gid,
                            float* __restrict__ pool, int N) {
    int c  = threadIdx.x;
    int n0 = blockIdx.x * 128;
    if (n0 >= N) return;
    int curg = __ldg(gid + n0);
    float acc = 0.f;
    #pragma unroll 4
    for (int i = 0; i < 128; ++i) {
        int n = n0 + i;
        if (n >= N) break;
        int g = __ldg(gid + n);
        if (g != curg) {
            atomicAdd(&pool[(size_t)curg * DF + c], acc);
            acc = 0.f;
            curg = g;
        }
        acc += __half2float(h16[(size_t)n * DF + c]);
    }
    atomicAdd(&pool[(size_t)curg * DF + c], acc);
}

// ---------------------------------------------------------------------------
__global__ void head_kernel(const float* __restrict__ pool, const float* __restrict__ desc,
                            const float* __restrict__ fc1W, const float* __restrict__ fc1b,
                            const float* __restrict__ n1g, const float* __restrict__ n1b,
                            const float* __restrict__ fc2W, const float* __restrict__ fc2b,
                            float* __restrict__ out, int X, int C) {
    int g = blockIdx.x;
    int t = threadIdx.x;
    int warp = t >> 5, lane = t & 31;

    __shared__ float xin[DF + 64];
    __shared__ float ss[4], qq[4];

    xin[t] = pool[(size_t)g * DF + t];
    if (t < X) xin[DF + t] = desc[(size_t)g * X + t];
    __syncthreads();

    int K = DF + X;
    float acc = fc1b[t];
    for (int k = 0; k < K; ++k)
        acc = fmaf(xin[k], __ldg(fc1W + (size_t)k * DF + t), acc);

    float s = acc, q = acc * acc;
    #pragma unroll
    for (int off = 16; off > 0; off >>= 1) {
        s += __shfl_xor_sync(0xFFFFFFFFu, s, off);
        q += __shfl_xor_sync(0xFFFFFFFFu, q, off);
    }
    if (lane == 0) { ss[warp] = s; qq[warp] = q; }
    __syncthreads();
    s = ss[0] + ss[1] + ss[2] + ss[3];
    q = qq[0] + qq[1] + qq[2] + qq[3];
    float mu   = s * (1.0f / 128.0f);
    float var  = q * (1.0f / 128.0f) - mu * mu;
    float rstd = rsqrtf(var + 1e-5f);
    float y = fmaxf(0.f, (acc - mu) * rstd * n1g[t] + n1b[t]);

    for (int c = 0; c < C; ++c) {
        float p = y * __ldg(fc2W + (size_t)t * C + c);
        #pragma unroll
        for (int off = 16; off > 0; off >>= 1)
            p += __shfl_xor_sync(0xFFFFFFFFu, p, off);
        __syncthreads();
        if (lane == 0) ss[warp] = p;
        __syncthreads();
        if (t == 0) out[(size_t)g * C + c] = ss[0] + ss[1] + ss[2] + ss[3] + fc2b[c];
    }
}

// ---------------------------------------------------------------------------
extern "C" void kernel_launch(void* const* d_in, const int* in_sizes, int n_in,
                              void* d_out, int out_size) {
    const float* h    = (const float*)d_in[0];
    const float* desc = (const float*)d_in[1];
    const int*   src  = (const int*)d_in[2];
    const int*   dst  = (const int*)d_in[3];
    const int*   gid  = (const int*)d_in[4];
    const float* W1   = (const float*)d_in[5];
    const float* b1   = (const float*)d_in[6];
    const float* g1   = (const float*)d_in[7];
    const float* be1  = (const float*)d_in[8];
    const float* W2   = (const float*)d_in[9];
    const float* b2   = (const float*)d_in[10];
    const float* eps  = (const float*)d_in[11];
    const float* ng   = (const float*)d_in[12];
    const float* nb   = (const float*)d_in[13];
    const float* fc1W = (const float*)d_in[14];
    const float* fc1b = (const float*)d_in[15];
    const float* n1g  = (const float*)d_in[16];
    const float* n1b  = (const float*)d_in[17];
    const float* fc2W = (const float*)d_in[18];
    const float* fc2b = (const float*)d_in[19];
    float* out = (float*)d_out;

    int N = in_sizes[0] / DF;
    int E = in_sizes[2];
    int L = in_sizes[11];
    int X = in_sizes[14] / DF - DF;
    if (X <= 0) X = 16;
    int G = in_sizes[1] / X;
    int C = in_sizes[18] / DF;
    if (C <= 0) C = 1;
    if (N > NMAX) N = NMAX;
    if (G > GMAX) G = GMAX;
    if (E > EMAX) E = EMAX;

    float *pool;
    __half *h16a, *h16b;
    int *degp, *rowptr, *cursor, *csrc, *bsum;
    cudaGetSymbolAddress((void**)&h16a, g_h16a);
    cudaGetSymbolAddress((void**)&h16b, g_h16b);
    cudaGetSymbolAddress((void**)&pool, g_pool);
    cudaGetSymbolAddress((void**)&degp, g_deg);
    cudaGetSymbolAddress((void**)&rowptr, g_rowptr);
    cudaGetSymbolAddress((void**)&cursor, g_cursor);
    cudaGetSymbolAddress((void**)&csrc, g_csrc);
    cudaGetSymbolAddress((void**)&bsum, g_bsum);

    const int SMEM_BYTES = (2 * 128 * 128 + 4 * 128 * XS_STRIDE) * 2 + 6 * DF * 4; // 216,064
    cudaFuncSetAttribute(layer_fused,
                         cudaFuncAttributeMaxDynamicSharedMemorySize, SMEM_BYTES);

    // --- CSR build + fp16 convert of input h (once per launch) ---
    int nb_scan = (N + 1023) / 1024;
    cudaMemsetAsync(degp, 0, (size_t)N * sizeof(int));
    deg_kernel<<<(E + 255) / 256, 256>>>(dst, degp, E);
    scan1_kernel<<<nb_scan, 1024>>>(degp, rowptr, bsum, N);
    scan2_kernel<<<1, 32>>>(bsum, nb_scan);
    scan3_kernel<<<nb_scan, 1024>>>(rowptr, bsum, cursor, N, E);
    scatter_kernel<<<(E + 255) / 256, 256>>>(src, dst, cursor, csrc, E);
    int nd4 = N * (DF / 4);
    cvt16_kernel<<<(nd4 + 255) / 256, 256>>>(h, h16a, nd4);

    int ntiles = (N + 127) / 128;
    int fgrid = ntiles < 148 ? ntiles : 148;

    __half* hin  = h16a;
    __half* hout = h16b;
    for (int l = 0; l < L; ++l) {
        layer_fused<<<fgrid, 1024, SMEM_BYTES>>>(
            hin, rowptr, csrc, eps, l,
            W1 + (size_t)l * DF * DF, b1 + (size_t)l * DF,
            g1 + (size_t)l * DF, be1 + (size_t)l * DF,
            W2 + (size_t)l * DF * DF, b2 + (size_t)l * DF,
            ng + (size_t)l * DF, nb + (size_t)l * DF,
            hout, N, ntiles);
        __half* t = hin; hin = hout; hout = t;
    }

    cudaMemsetAsync(pool, 0, (size_t)G * DF * sizeof(float));
    pool_kernel<<<(N + 127) / 128, 128>>>(hin, gid, pool, N);
    head_kernel<<<G, 128>>>(pool, desc, fc1W, fc1b, n1g, n1b, fc2W, fc2b, out, X, C);
}